// round 12
// baseline (speedup 1.0000x reference)
#include <cuda_runtime.h>
#include <cuda_bf16.h>
#include <math.h>
#include <cstdint>

// RotationalConv2D v12 — GB300 sm_103a
// A0: channel-sum intensity image I[b,h,w].
// A1: per-patch centroid/angle from 25 I-loads (thread per patch).
// B : tf32 mma.sync main kernel (v11 + hoisted per-jy terms).

#define HDIM 128
#define CCH 16
#define FOUT 32
#define KK 5
#define HO 124
#define WO 124
#define NP (4 * HO * WO)     // 61504 = 961 * 64
#define HW (HO * WO)

__device__ float  g_int[4 * HDIM * HDIM];   // channel-sum image
__device__ float4 g_ang[NP];                // (co*s, si*s, xo*s, yo*s)
__device__ uint4  g_bfrag[25 * 4 * 32];     // [j][slot][lane]

__device__ __forceinline__ uint32_t f2tf32(float x) {
    uint32_t r;
    asm("cvt.rn.tf32.f32 %0, %1;" : "=r"(r) : "f"(x));
    return r;
}

__device__ __forceinline__ void mma_tf32(float* c,
                                         uint32_t a0, uint32_t a1,
                                         uint32_t a2, uint32_t a3,
                                         uint32_t b0, uint32_t b1) {
    asm volatile(
        "mma.sync.aligned.m16n8k8.row.col.f32.tf32.tf32.f32 "
        "{%0,%1,%2,%3}, {%4,%5,%6,%7}, {%8,%9}, {%0,%1,%2,%3};"
        : "+f"(c[0]), "+f"(c[1]), "+f"(c[2]), "+f"(c[3])
        : "r"(a0), "r"(a1), "r"(a2), "r"(a3), "r"(b0), "r"(b1));
}

// ---------------- A0: intensity image + W fragments ----------------
__global__ void __launch_bounds__(256)
rot_intens_kernel(const float* __restrict__ in, const float* __restrict__ Wg)
{
    const int i = blockIdx.x * 256 + threadIdx.x;   // 0 .. 65535
    const float4* p = reinterpret_cast<const float4*>(in + i * CCH);
    const float4 v0 = p[0], v1 = p[1], v2 = p[2], v3 = p[3];
    g_int[i] = (v0.x + v0.y + v0.z + v0.w) + (v1.x + v1.y + v1.z + v1.w)
             + (v2.x + v2.y + v2.z + v2.w) + (v3.x + v3.y + v3.z + v3.w);

    if (blockIdx.x == 0) {
        uint32_t* bf = reinterpret_cast<uint32_t*>(g_bfrag);
        for (int k = threadIdx.x; k < 25 * 4 * 32 * 4; k += 256) {
            const int r2  = k & 3;
            const int ln  = (k >> 2) & 31;
            const int ntp = (k >> 7) & 1;
            const int ks  = (k >> 8) & 1;
            const int j   = k >> 9;
            const int nt  = 2 * ntp + (r2 >> 1);
            const int r   = r2 & 1;
            bf[k] = f2tf32(Wg[(nt * 8 + (ln >> 2)) * 400 + j * 16 + 4 * (ln & 3) + 2 * ks + r]);
        }
    }
}

// ---------------- A1: per-patch angle from I ----------------
__global__ void __launch_bounds__(256)
rot_angles_kernel()
{
    const int P = blockIdx.x * 256 + threadIdx.x;
    if (P >= NP) return;
    const int b   = P / HW;
    const int rem = P - b * HW;
    const int ho  = rem / WO;
    const int wo  = rem - ho * WO;
    const float* ib = g_int + (b * HDIM + ho) * HDIM + wo;

    float tot = 0.f, sr = 0.f, sc = 0.f;
    #pragma unroll
    for (int r = 0; r < KK; r++) {
        #pragma unroll
        for (int cl = 0; cl < KK; cl++) {
            const float s = __ldg(ib + r * HDIM + cl);
            tot += s;
            sr  += s * (float)r;
            sc  += s * (float)cl;
        }
    }
    tot += 1e-7f;
    const float cr   = sr / tot;
    const float ccen = sc / tot;
    const float m    = (float)(KK - 1) * 0.5f;
    const float ang  = atan2f(cr - m, ccen - m + 1e-7f);
    const float co   = __cosf(ang);
    const float si   = __sinf(ang);
    const float km1  = (float)(KK - 1);
    const float scale = 1.0f / (1.0f + 1e-7f);
    g_ang[P] = make_float4(co * scale, si * scale,
                           (km1 - (co * km1 - si * km1)) * 0.5f * scale,
                           (km1 - (si * km1 + co * km1)) * 0.5f * scale);
}

// ---------------- B: main taps + mma ----------------
__global__ void __launch_bounds__(128, 5)
rotconv12_kernel(const float* __restrict__ in,
                 const float* __restrict__ bias,
                 float* __restrict__ out)
{
    const int tid  = threadIdx.x;
    const int wid  = tid >> 5;
    const int lane = tid & 31;
    const int q    = lane & 3;
    const int row  = lane >> 2;
    const int tb   = blockIdx.x * 64 + wid * 16;   // exact grid

    float co[2], si[2], xo[2], yo[2];
    const float* pbase[2];
    #pragma unroll
    for (int u = 0; u < 2; u++) {
        const int P   = tb + row + 8 * u;
        const float4 a = g_ang[P];
        co[u] = a.x; si[u] = a.y; xo[u] = a.z; yo[u] = a.w;
        const int b   = P / HW;
        const int rem = P - b * HW;
        const int ho  = rem / WO;
        const int wo  = rem - ho * WO;
        pbase[u] = in + ((b * HDIM + ho) * HDIM + wo) * CCH + q * 4;
    }

    float acc[4][4];
    #pragma unroll
    for (int nt = 0; nt < 4; nt++)
        #pragma unroll
        for (int k = 0; k < 4; k++) acc[nt][k] = 0.f;

    int j = 0;
    #pragma unroll 1
    for (int jy = 0; jy < KK; jy++) {
        const float gy = (float)jy;
        // hoist the gy-dependent terms per patch
        float Ax[2], By[2];
        #pragma unroll
        for (int u = 0; u < 2; u++) {
            Ax[u] = xo[u] - si[u] * gy;    // sx = co*gx + Ax
            By[u] = yo[u] + co[u] * gy;    // sy = si*gx + By
        }
        #pragma unroll 1
        for (int jx = 0; jx < KK; jx++, j++) {
            const float gx = (float)jx;

            const uint4* bp = g_bfrag + j * 4 * 32 + lane;
            const uint4 bk0a = __ldg(bp);
            const uint4 bk0b = __ldg(bp + 32);
            const uint4 bk1a = __ldg(bp + 64);
            const uint4 bk1b = __ldg(bp + 96);

            uint32_t ra[2][4];
            #pragma unroll
            for (int u = 0; u < 2; u++) {
                const float sx  = co[u] * gx + Ax[u];
                const float sy  = si[u] * gx + By[u];
                const float x0f = floorf(sx);
                const float y0f = floorf(sy);
                const float wx  = sx - x0f;
                const float wy  = sy - y0f;
                const int   x0  = (int)x0f;
                const int   y0  = (int)y0f;
                const int   x1  = x0 + 1;
                const int   y1  = y0 + 1;

                const bool vx0 = (unsigned)x0 < KK;
                const bool vx1 = (unsigned)x1 < KK;
                const bool vy0 = (unsigned)y0 < KK;
                const bool vy1 = (unsigned)y1 < KK;
                const int x0c = min(max(x0, 0), KK - 1);
                const int x1c = min(max(x1, 0), KK - 1);
                const int y0c = min(max(y0, 0), KK - 1);
                const int y1c = min(max(y1, 0), KK - 1);

                const float wx1 = 1.f - wx;
                const float wy1 = 1.f - wy;
                const float w00 = (vx0 && vy0) ? wx1 * wy1 : 0.f;
                const float w01 = (vx1 && vy0) ? wx  * wy1 : 0.f;
                const float w10 = (vx0 && vy1) ? wx1 * wy  : 0.f;
                const float w11 = (vx1 && vy1) ? wx  * wy  : 0.f;

                const float* r0 = pbase[u] + y0c * (HDIM * CCH);
                const float* r1 = pbase[u] + y1c * (HDIM * CCH);
                const float4 v00 = *reinterpret_cast<const float4*>(r0 + x0c * CCH);
                const float4 v01 = *reinterpret_cast<const float4*>(r0 + x1c * CCH);
                const float4 v10 = *reinterpret_cast<const float4*>(r1 + x0c * CCH);
                const float4 v11 = *reinterpret_cast<const float4*>(r1 + x1c * CCH);

                ra[u][0] = f2tf32(w00 * v00.x + w01 * v01.x + w10 * v10.x + w11 * v11.x);
                ra[u][1] = f2tf32(w00 * v00.y + w01 * v01.y + w10 * v10.y + w11 * v11.y);
                ra[u][2] = f2tf32(w00 * v00.z + w01 * v01.z + w10 * v10.z + w11 * v11.z);
                ra[u][3] = f2tf32(w00 * v00.w + w01 * v01.w + w10 * v10.w + w11 * v11.w);
            }

            mma_tf32(acc[0], ra[0][0], ra[1][0], ra[0][1], ra[1][1], bk0a.x, bk0a.y);
            mma_tf32(acc[1], ra[0][0], ra[1][0], ra[0][1], ra[1][1], bk0a.z, bk0a.w);
            mma_tf32(acc[2], ra[0][0], ra[1][0], ra[0][1], ra[1][1], bk0b.x, bk0b.y);
            mma_tf32(acc[3], ra[0][0], ra[1][0], ra[0][1], ra[1][1], bk0b.z, bk0b.w);
            mma_tf32(acc[0], ra[0][2], ra[1][2], ra[0][3], ra[1][3], bk1a.x, bk1a.y);
            mma_tf32(acc[1], ra[0][2], ra[1][2], ra[0][3], ra[1][3], bk1a.z, bk1a.w);
            mma_tf32(acc[2], ra[0][2], ra[1][2], ra[0][3], ra[1][3], bk1b.x, bk1b.y);
            mma_tf32(acc[3], ra[0][2], ra[1][2], ra[0][3], ra[1][3], bk1b.z, bk1b.w);
        }
    }

    const float2 bv0 = *reinterpret_cast<const float2*>(bias + 0  + 2 * q);
    const float2 bv1 = *reinterpret_cast<const float2*>(bias + 8  + 2 * q);
    const float2 bv2 = *reinterpret_cast<const float2*>(bias + 16 + 2 * q);
    const float2 bv3 = *reinterpret_cast<const float2*>(bias + 24 + 2 * q);
    const float2 bvs[4] = { bv0, bv1, bv2, bv3 };
    #pragma unroll
    for (int nt = 0; nt < 4; nt++) {
        float* o0 = out + (tb + row) * FOUT + nt * 8 + 2 * q;
        float* o1 = out + (tb + row + 8) * FOUT + nt * 8 + 2 * q;
        float2 v0, v1;
        v0.x = acc[nt][0] + bvs[nt].x;  v0.y = acc[nt][1] + bvs[nt].y;
        v1.x = acc[nt][2] + bvs[nt].x;  v1.y = acc[nt][3] + bvs[nt].y;
        *reinterpret_cast<float2*>(o0) = v0;
        *reinterpret_cast<float2*>(o1) = v1;
    }
}

extern "C" void kernel_launch(void* const* d_in, const int* in_sizes, int n_in,
                              void* d_out, int out_size)
{
    const float* in   = (const float*)d_in[0];   // [4,128,128,16]
    const float* Wg   = (const float*)d_in[1];   // [32,5,5,16]
    const float* bias = (const float*)d_in[2];   // [32]
    float* out = (float*)d_out;                  // [4,124,124,32]

    rot_intens_kernel<<<(4 * HDIM * HDIM) / 256, 256>>>(in, Wg);   // 256 blocks
    rot_angles_kernel<<<(NP + 255) / 256, 256>>>();                // 241 blocks
    rotconv12_kernel<<<NP / 64, 128>>>(in, bias, out);             // 961 blocks
}